// round 2
// baseline (speedup 1.0000x reference)
#include <cuda_runtime.h>

// Problem constants
#define B_  4
#define T_  2048
#define C_  768
#define H_  12
#define D_  64
#define M_  (B_ * T_)          // 8192 rows for the projection GEMMs

// Scratch (device globals: allocation-guard-safe)
__device__ float g_Q[(size_t)B_ * H_ * T_ * D_];   // [B,H,T,D]
__device__ float g_K[(size_t)B_ * H_ * T_ * D_];   // [B,H,T,D]
__device__ float g_V[(size_t)B_ * H_ * T_ * D_];   // [B,H,T,D]
__device__ float g_O[(size_t)B_ * T_ * C_];        // [B,T,C] attention output

// ---------------------------------------------------------------------------
// SGEMM core: 128x128 tile, K-step 8, 256 threads, 8x8 microtile per thread.
// A: [M,768] row-major, W: [768,768] row-major. Fills acc[8][8].
// ---------------------------------------------------------------------------
__device__ __forceinline__ void sgemm_core(const float* __restrict__ A,
                                           const float* __restrict__ W,
                                           float (*As)[128], float (*Bs)[128],
                                           float acc[8][8],
                                           int bm, int bn)
{
    const int tid  = threadIdx.x;
    const int arow = tid >> 1;            // 0..127
    const int ak   = (tid & 1) * 4;       // 0 or 4
    const int bk   = tid >> 5;            // 0..7
    const int bn4  = (tid & 31) * 4;      // 0..124
    const int rm   = (tid >> 4) * 8;      // 0..120
    const int rn   = (tid & 15) * 8;      // 0..120

    for (int k0 = 0; k0 < C_; k0 += 8) {
        float4 av = *(const float4*)&A[(size_t)(bm + arow) * C_ + k0 + ak];
        float4 bv = *(const float4*)&W[(size_t)(k0 + bk) * C_ + bn + bn4];
        __syncthreads();                 // previous iteration consumers done
        As[ak + 0][arow] = av.x;
        As[ak + 1][arow] = av.y;
        As[ak + 2][arow] = av.z;
        As[ak + 3][arow] = av.w;
        *(float4*)&Bs[bk][bn4] = bv;
        __syncthreads();

        #pragma unroll
        for (int kk = 0; kk < 8; kk++) {
            float a[8], b[8];
            *(float4*)&a[0] = *(const float4*)&As[kk][rm];
            *(float4*)&a[4] = *(const float4*)&As[kk][rm + 4];
            *(float4*)&b[0] = *(const float4*)&Bs[kk][rn];
            *(float4*)&b[4] = *(const float4*)&Bs[kk][rn + 4];
            #pragma unroll
            for (int i = 0; i < 8; i++)
                #pragma unroll
                for (int j = 0; j < 8; j++)
                    acc[i][j] += a[i] * b[j];
        }
    }
}

// ---------------------------------------------------------------------------
// Kernel 1: QKV projections. grid = (N/128=6, M/128=64, 3); z picks Q/K/V.
// Epilogue permutes [B,T,H,D] -> [B,H,T,D].
// ---------------------------------------------------------------------------
__global__ __launch_bounds__(256)
void qkv_gemm_kernel(const float* __restrict__ X,
                     const float* __restrict__ Wq, const float* __restrict__ bq,
                     const float* __restrict__ Wk, const float* __restrict__ bk,
                     const float* __restrict__ Wv, const float* __restrict__ bv)
{
    __shared__ float As[8][128];
    __shared__ float Bs[8][128];

    const float* W;
    const float* bias;
    float* out;
    if (blockIdx.z == 0)      { W = Wq; bias = bq; out = g_Q; }
    else if (blockIdx.z == 1) { W = Wk; bias = bk; out = g_K; }
    else                      { W = Wv; bias = bv; out = g_V; }

    const int bm = blockIdx.y * 128;
    const int bn = blockIdx.x * 128;

    float acc[8][8];
    #pragma unroll
    for (int i = 0; i < 8; i++)
        #pragma unroll
        for (int j = 0; j < 8; j++) acc[i][j] = 0.f;

    sgemm_core(X, W, As, Bs, acc, bm, bn);

    const int rm = ((threadIdx.x >> 4) * 8);
    const int rn = ((threadIdx.x & 15) * 8);
    #pragma unroll
    for (int i = 0; i < 8; i++) {
        const int m  = bm + rm + i;
        const int bi = m >> 11;          // m / T_
        const int t  = m & (T_ - 1);
        #pragma unroll
        for (int j = 0; j < 8; j++) {
            const int n = bn + rn + j;
            const int h = n >> 6;        // n / D_
            const int d = n & (D_ - 1);
            out[(((size_t)bi * H_ + h) * T_ + t) * D_ + d] = acc[i][j] + bias[n];
        }
    }
}

// ---------------------------------------------------------------------------
// Kernel 2: causal flash attention, fp32.
// grid = (T/128 = 16, B*H = 48), 128 threads, 1 query row / thread.
// Writes O in [B,T,H,D] == [B,T,C] layout for the final GEMM.
// ---------------------------------------------------------------------------
__global__ __launch_bounds__(128)
void flash_attn_kernel()
{
    const int bh  = blockIdx.y;           // 0..47
    const int qt  = blockIdx.x;           // 0..15
    const int tid = threadIdx.x;
    const int qi  = qt * 128 + tid;       // global query index (< T_)

    const float* Qp    = &g_Q[((size_t)bh * T_ + qi) * D_];
    const float* Kbase = &g_K[(size_t)bh * T_ * D_];
    const float* Vbase = &g_V[(size_t)bh * T_ * D_];

    float q[D_];
    #pragma unroll
    for (int d = 0; d < D_; d += 4) {
        float4 v = *(const float4*)&Qp[d];
        q[d + 0] = v.x * 0.125f;          // 1/sqrt(64) folded into q
        q[d + 1] = v.y * 0.125f;
        q[d + 2] = v.z * 0.125f;
        q[d + 3] = v.w * 0.125f;
    }

    float acc[D_];
    #pragma unroll
    for (int d = 0; d < D_; d++) acc[d] = 0.f;
    float mrun = -1e30f, lrun = 0.f;

    __shared__ float Ks[32][64];
    __shared__ float Vs[32][64];

    const int kend = qt * 128 + 127;      // max key needed by this block

    for (int kt = 0; kt <= kend; kt += 32) {
        __syncthreads();
        // Cooperative tile load: 2048 floats each = 512 float4, 4 per thread
        #pragma unroll
        for (int i = 0; i < 4; i++) {
            const int e  = tid + i * 128;      // 0..511
            const int r  = e >> 4;             // 0..31
            const int c4 = (e & 15) << 2;      // 0..60
            *(float4*)&Ks[r][c4] = *(const float4*)&Kbase[(size_t)(kt + r) * D_ + c4];
            *(float4*)&Vs[r][c4] = *(const float4*)&Vbase[(size_t)(kt + r) * D_ + c4];
        }
        __syncthreads();

        float s[32];
        float tmax = -1e30f;
        #pragma unroll
        for (int j = 0; j < 32; j++) {
            float dot = 0.f;
            #pragma unroll
            for (int d = 0; d < D_; d++) dot += q[d] * Ks[j][d];
            s[j] = (kt + j <= qi) ? dot : -1e30f;
            tmax = fmaxf(tmax, s[j]);
        }

        const float mnew = fmaxf(mrun, tmax);
        const float corr = __expf(mrun - mnew);
        float psum = 0.f;
        #pragma unroll
        for (int j = 0; j < 32; j++) {
            s[j] = __expf(s[j] - mnew);
            psum += s[j];
        }
        lrun = lrun * corr + psum;
        mrun = mnew;

        #pragma unroll
        for (int d = 0; d < D_; d++) acc[d] *= corr;
        #pragma unroll
        for (int j = 0; j < 32; j++) {
            const float p = s[j];
            #pragma unroll
            for (int d = 0; d < D_; d++) acc[d] += p * Vs[j][d];
        }
    }

    const float inv = 1.f / lrun;
    const int bi = bh / H_;
    const int h  = bh % H_;
    float* Op = &g_O[(((size_t)bi * T_ + qi) * H_ + h) * D_];
    #pragma unroll
    for (int d = 0; d < D_; d += 4) {
        float4 v;
        v.x = acc[d + 0] * inv;
        v.y = acc[d + 1] * inv;
        v.z = acc[d + 2] * inv;
        v.w = acc[d + 3] * inv;
        *(float4*)&Op[d] = v;
    }
}

// ---------------------------------------------------------------------------
// Kernel 3: output projection. Plain row-major epilogue into d_out.
// ---------------------------------------------------------------------------
__global__ __launch_bounds__(256)
void out_gemm_kernel(const float* __restrict__ Wo, const float* __restrict__ bo,
                     float* __restrict__ out)
{
    __shared__ float As[8][128];
    __shared__ float Bs[8][128];

    const int bm = blockIdx.y * 128;
    const int bn = blockIdx.x * 128;

    float acc[8][8];
    #pragma unroll
    for (int i = 0; i < 8; i++)
        #pragma unroll
        for (int j = 0; j < 8; j++) acc[i][j] = 0.f;

    sgemm_core(g_O, Wo, As, Bs, acc, bm, bn);

    const int rm = ((threadIdx.x >> 4) * 8);
    const int rn = ((threadIdx.x & 15) * 8);
    #pragma unroll
    for (int i = 0; i < 8; i++) {
        const int m = bm + rm + i;
        #pragma unroll
        for (int j = 0; j < 8; j += 4) {
            const int n = bn + rn + j;
            float4 v;
            v.x = acc[i][j + 0] + bo[n + 0];
            v.y = acc[i][j + 1] + bo[n + 1];
            v.z = acc[i][j + 2] + bo[n + 2];
            v.w = acc[i][j + 3] + bo[n + 3];
            *(float4*)&out[(size_t)m * C_ + n] = v;
        }
    }
}

// ---------------------------------------------------------------------------
// Launch
// ---------------------------------------------------------------------------
extern "C" void kernel_launch(void* const* d_in, const int* in_sizes, int n_in,
                              void* d_out, int out_size)
{
    const float* x  = (const float*)d_in[0];
    const float* Wq = (const float*)d_in[1];
    const float* bq = (const float*)d_in[2];
    const float* Wk = (const float*)d_in[3];
    const float* bk = (const float*)d_in[4];
    const float* Wv = (const float*)d_in[5];
    const float* bv = (const float*)d_in[6];
    const float* Wo = (const float*)d_in[7];
    const float* bo = (const float*)d_in[8];

    dim3 gq(C_ / 128, M_ / 128, 3);               // (6, 64, 3)
    qkv_gemm_kernel<<<gq, 256>>>(x, Wq, bq, Wk, bk, Wv, bv);

    dim3 ga(T_ / 128, B_ * H_);                   // (16, 48)
    flash_attn_kernel<<<ga, 128>>>();

    dim3 go(C_ / 128, M_ / 128);                  // (6, 64)
    out_gemm_kernel<<<go, 256>>>(Wo, bo, (float*)d_out);
}

// round 4
// speedup vs baseline: 1.3006x; 1.3006x over previous
#include <cuda_runtime.h>
#include <cuda_bf16.h>
#include <cstdint>

// ---------------------------------------------------------------------------
// Problem constants
// ---------------------------------------------------------------------------
#define B_  4
#define T_  2048
#define C_  768
#define H_  12
#define D_  64
#define M_  (B_ * T_)          // 8192

// ---------------------------------------------------------------------------
// Scratch device globals (allocation-guard-safe)
// ---------------------------------------------------------------------------
__device__ float g_Q[(size_t)B_ * H_ * T_ * D_];   // [B,H,T,D] fp32
__device__ float g_K[(size_t)B_ * H_ * T_ * D_];
__device__ float g_V[(size_t)B_ * H_ * T_ * D_];
__device__ float g_O[(size_t)B_ * T_ * C_];        // [B,T,C] fp32 attn out

__device__ __nv_bfloat16 g_Xhi[(size_t)M_ * C_];
__device__ __nv_bfloat16 g_Xlo[(size_t)M_ * C_];
__device__ __nv_bfloat16 g_Whi[4 * (size_t)C_ * C_];   // Wq,Wk,Wv,Wo
__device__ __nv_bfloat16 g_Wlo[4 * (size_t)C_ * C_];
__device__ __nv_bfloat16 g_Ohi[(size_t)M_ * C_];
__device__ __nv_bfloat16 g_Olo[(size_t)M_ * C_];

// ---------------------------------------------------------------------------
// Warp-MMA helpers (base compute_103 features only: sm_80-era PTX)
// ---------------------------------------------------------------------------
__device__ __forceinline__ uint32_t smem_u32(const void* p) {
    uint32_t a;
    asm("{ .reg .u64 t; cvta.to.shared.u64 t, %1; cvt.u32.u64 %0, t; }"
        : "=r"(a) : "l"(p));
    return a;
}

__device__ __forceinline__ void ldsm_x4(uint32_t* r, uint32_t addr) {
    asm volatile("ldmatrix.sync.aligned.m8n8.x4.shared.b16 {%0,%1,%2,%3}, [%4];"
                 : "=r"(r[0]), "=r"(r[1]), "=r"(r[2]), "=r"(r[3]) : "r"(addr));
}

__device__ __forceinline__ void ldsm_x4_trans(uint32_t* r, uint32_t addr) {
    asm volatile("ldmatrix.sync.aligned.m8n8.x4.trans.shared.b16 {%0,%1,%2,%3}, [%4];"
                 : "=r"(r[0]), "=r"(r[1]), "=r"(r[2]), "=r"(r[3]) : "r"(addr));
}

__device__ __forceinline__ void mma_bf16(float* c, const uint32_t* a, const uint32_t* b) {
    asm volatile(
        "mma.sync.aligned.m16n8k16.row.col.f32.bf16.bf16.f32 "
        "{%0,%1,%2,%3}, {%4,%5,%6,%7}, {%8,%9}, {%0,%1,%2,%3};"
        : "+f"(c[0]), "+f"(c[1]), "+f"(c[2]), "+f"(c[3])
        : "r"(a[0]), "r"(a[1]), "r"(a[2]), "r"(a[3]), "r"(b[0]), "r"(b[1]));
}

// ---------------------------------------------------------------------------
// Split-precision converters
// ---------------------------------------------------------------------------
__global__ void cvt_x_kernel(const float* __restrict__ src) {
    size_t i = (size_t)blockIdx.x * blockDim.x + threadIdx.x;
    float v = src[i];
    __nv_bfloat16 h = __float2bfloat16(v);
    g_Xhi[i] = h;
    g_Xlo[i] = __float2bfloat16(v - __bfloat162float(h));
}

__global__ void cvt_w_kernel(const float* __restrict__ Wq, const float* __restrict__ Wk,
                             const float* __restrict__ Wv, const float* __restrict__ Wo) {
    const float* src = (blockIdx.y == 0) ? Wq : (blockIdx.y == 1) ? Wk
                      : (blockIdx.y == 2) ? Wv : Wo;
    size_t off = (size_t)blockIdx.y * C_ * C_;
    size_t i = (size_t)blockIdx.x * blockDim.x + threadIdx.x;
    float v = src[i];
    __nv_bfloat16 h = __float2bfloat16(v);
    g_Whi[off + i] = h;
    g_Wlo[off + i] = __float2bfloat16(v - __bfloat162float(h));
}

__global__ void cvt_o_kernel() {
    size_t i = (size_t)blockIdx.x * blockDim.x + threadIdx.x;
    float v = g_O[i];
    __nv_bfloat16 h = __float2bfloat16(v);
    g_Ohi[i] = h;
    g_Olo[i] = __float2bfloat16(v - __bfloat162float(h));
}

// ---------------------------------------------------------------------------
// GEMM via mma.sync: out[m][n] = sum_k A[m][k]*W[k][n] + bias[n]
// CTA 128(M)x128(N), BK=32, 256 threads (8 warps, warp tile 32x64),
// double-buffered smem, split-precision bf16 (3 MMAs per tile pair).
//
// Smem layout per stage (bytes):
//   A_hi[128][40 bf16] @ 0      (row stride 80B  = 5x16B  -> ldmatrix conflict-free)
//   A_lo               @ 10240
//   B_hi[32][136 bf16] @ 20480  (row stride 272B = 17x16B -> conflict-free)
//   B_lo               @ 29184
// stage size 37888, x2 = 75776 bytes dynamic smem.
// ---------------------------------------------------------------------------
#define BK      32
#define NCHUNK  (C_ / BK)      // 24
#define A_STRIDE 80
#define B_STRIDE 272
#define SM_ALO   10240
#define SM_BHI   20480
#define SM_BLO   29184
#define SM_STAGE 37888
#define SM_TOTAL (2 * SM_STAGE)

__global__ __launch_bounds__(256, 1)
void tc_gemm_kernel(int mode, float* __restrict__ out_final,
                    const float* __restrict__ b0, const float* __restrict__ b1,
                    const float* __restrict__ b2)
{
    extern __shared__ char smem[];
    const uint32_t sb = smem_u32(smem);
    const int tid  = threadIdx.x;
    const int lane = tid & 31;
    const int w    = tid >> 5;
    const int wm   = (w & 3) * 32;     // warp m offset in CTA tile
    const int wn   = (w >> 2) * 64;    // warp n offset

    const int z    = blockIdx.z;
    const int widx = (mode == 0) ? z : 3;
    const __nv_bfloat16* Ahi = (mode == 0) ? g_Xhi : g_Ohi;
    const __nv_bfloat16* Alo = (mode == 0) ? g_Xlo : g_Olo;
    const __nv_bfloat16* Whi = g_Whi + (size_t)widx * C_ * C_;
    const __nv_bfloat16* Wlo = g_Wlo + (size_t)widx * C_ * C_;
    const float* bias = (mode == 0) ? ((z == 0) ? b0 : (z == 1) ? b1 : b2) : b0;

    const int bm = blockIdx.y * 128;
    const int bn = blockIdx.x * 128;

    float acc[2][8][4];
    #pragma unroll
    for (int i = 0; i < 2; i++)
        #pragma unroll
        for (int j = 0; j < 8; j++)
            #pragma unroll
            for (int r = 0; r < 4; r++) acc[i][j][r] = 0.f;

    // global-load coordinates
    const int au = tid & 3;            // 16B unit in A row (4 x 8 bf16 = 32 k)
    const int ar = tid >> 2;           // 0..63 (rows ar, ar+64)
    const int bu = tid & 15;           // 16B unit in B row (16 x 8 bf16 = 128 n)
    const int br = tid >> 4;           // 0..15 (rows br, br+16)

    // ldmatrix base addresses (per-lane)
    const uint32_t aAddr0 = (uint32_t)((wm + (lane & 15)) * A_STRIDE + (lane >> 4) * 16);
    const uint32_t bAddr0 = (uint32_t)(((lane & 7) + ((lane >> 3) & 1) * 8) * B_STRIDE
                                       + (wn + (lane >> 4) * 8) * 2);

    // ---- prologue: load chunk 0 into stage 0 ----
    {
        const int k0 = 0;
        #pragma unroll
        for (int h = 0; h < 2; h++) {
            const int row = ar + h * 64;
            const size_t ga = (size_t)(bm + row) * C_ + k0 + au * 8;
            *(uint4*)(smem + row * A_STRIDE + au * 16)          = *(const uint4*)(Ahi + ga);
            *(uint4*)(smem + SM_ALO + row * A_STRIDE + au * 16) = *(const uint4*)(Alo + ga);
        }
        #pragma unroll
        for (int h = 0; h < 2; h++) {
            const int row = br + h * 16;
            const size_t gb = (size_t)(k0 + row) * C_ + bn + bu * 8;
            *(uint4*)(smem + SM_BHI + row * B_STRIDE + bu * 16) = *(const uint4*)(Whi + gb);
            *(uint4*)(smem + SM_BLO + row * B_STRIDE + bu * 16) = *(const uint4*)(Wlo + gb);
        }
    }
    __syncthreads();

    for (int c = 0; c < NCHUNK; ++c) {
        // ---- issue next chunk's global loads (latency overlaps the MMAs) ----
        uint4 nAhi[2], nAlo[2], nBhi[2], nBlo[2];
        if (c + 1 < NCHUNK) {
            const int k0 = (c + 1) * BK;
            #pragma unroll
            for (int h = 0; h < 2; h++) {
                const int row = ar + h * 64;
                const size_t ga = (size_t)(bm + row) * C_ + k0 + au * 8;
                nAhi[h] = *(const uint4*)(Ahi + ga);
                nAlo[h] = *(const uint4*)(Alo + ga);
            }
            #pragma unroll
            for (int h = 0; h < 2; h++) {
                const int row = br + h * 16;
                const size_t gb = (size_t)(k0 + row) * C_ + bn + bu * 8;
                nBhi[h] = *(const uint4*)(Whi + gb);
                nBlo[h] = *(const uint4*)(Wlo + gb);
            }
        }

        // ---- compute current stage ----
        const uint32_t stg = sb + (c & 1) * SM_STAGE;
        #pragma unroll
        for (int kk = 0; kk < 2; kk++) {
            uint32_t ah[2][4], al[2][4], bh[8][2], bl[8][2];
            #pragma unroll
            for (int i = 0; i < 2; i++) {
                const uint32_t aoff = aAddr0 + i * 16 * A_STRIDE + kk * 32;
                ldsm_x4(ah[i], stg + aoff);
                ldsm_x4(al[i], stg + SM_ALO + aoff);
            }
            #pragma unroll
            for (int jj = 0; jj < 4; jj++) {
                uint32_t t[4];
                const uint32_t boff = bAddr0 + kk * 16 * B_STRIDE + jj * 32;
                ldsm_x4_trans(t, stg + SM_BHI + boff);
                bh[jj * 2][0] = t[0]; bh[jj * 2][1] = t[1];
                bh[jj * 2 + 1][0] = t[2]; bh[jj * 2 + 1][1] = t[3];
                ldsm_x4_trans(t, stg + SM_BLO + boff);
                bl[jj * 2][0] = t[0]; bl[jj * 2][1] = t[1];
                bl[jj * 2 + 1][0] = t[2]; bl[jj * 2 + 1][1] = t[3];
            }
            #pragma unroll
            for (int i = 0; i < 2; i++)
                #pragma unroll
                for (int j = 0; j < 8; j++) {
                    mma_bf16(acc[i][j], ah[i], bh[j]);
                    mma_bf16(acc[i][j], ah[i], bl[j]);
                    mma_bf16(acc[i][j], al[i], bh[j]);
                }
        }

        // ---- store next chunk into the other stage ----
        if (c + 1 < NCHUNK) {
            char* dst = smem + ((c + 1) & 1) * SM_STAGE;
            #pragma unroll
            for (int h = 0; h < 2; h++) {
                const int row = ar + h * 64;
                *(uint4*)(dst + row * A_STRIDE + au * 16)          = nAhi[h];
                *(uint4*)(dst + SM_ALO + row * A_STRIDE + au * 16) = nAlo[h];
            }
            #pragma unroll
            for (int h = 0; h < 2; h++) {
                const int row = br + h * 16;
                *(uint4*)(dst + SM_BHI + row * B_STRIDE + bu * 16) = nBhi[h];
                *(uint4*)(dst + SM_BLO + row * B_STRIDE + bu * 16) = nBlo[h];
            }
        }
        __syncthreads();
    }

    // ---- epilogue ----
    #pragma unroll
    for (int i = 0; i < 2; i++) {
        const int r0 = bm + wm + i * 16 + (lane >> 2);
        #pragma unroll
        for (int j = 0; j < 8; j++) {
            const int col = bn + wn + j * 8 + (lane & 3) * 2;
            const float bx = bias[col], by = bias[col + 1];
            if (mode == 0) {
                const int h = col >> 6;          // head within this 128-wide tile span
                const int d = col & 63;
                float* base = (z == 0) ? g_Q : (z == 1) ? g_K : g_V;
                #pragma unroll
                for (int half = 0; half < 2; half++) {
                    const int m  = r0 + half * 8;
                    const int bi = m >> 11;
                    const int tt = m & (T_ - 1);
                    float2 v = make_float2(acc[i][j][half * 2] + bx,
                                           acc[i][j][half * 2 + 1] + by);
                    *(float2*)(base + (((size_t)bi * H_ + h) * T_ + tt) * D_ + d) = v;
                }
            } else {
                #pragma unroll
                for (int half = 0; half < 2; half++) {
                    const int m = r0 + half * 8;
                    float2 v = make_float2(acc[i][j][half * 2] + bx,
                                           acc[i][j][half * 2 + 1] + by);
                    *(float2*)(out_final + (size_t)m * C_ + col) = v;
                }
            }
        }
    }
}

// ---------------------------------------------------------------------------
// Causal flash attention, fp32, float4 smem reads.
// grid = (T/128, B*H), 128 threads, 1 query row / thread.
// ---------------------------------------------------------------------------
__global__ __launch_bounds__(128, 2)
void flash_attn_kernel()
{
    const int bh  = blockIdx.y;
    const int qt  = blockIdx.x;
    const int tid = threadIdx.x;
    const int qi  = qt * 128 + tid;

    const float* Qp    = &g_Q[((size_t)bh * T_ + qi) * D_];
    const float* Kbase = &g_K[(size_t)bh * T_ * D_];
    const float* Vbase = &g_V[(size_t)bh * T_ * D_];

    const float qscale = 0.125f * 1.4426950408889634f;   // 1/sqrt(64) * log2(e)
    float q[D_];
    #pragma unroll
    for (int d = 0; d < D_; d += 4) {
        float4 v = *(const float4*)&Qp[d];
        q[d + 0] = v.x * qscale;
        q[d + 1] = v.y * qscale;
        q[d + 2] = v.z * qscale;
        q[d + 3] = v.w * qscale;
    }

    float acc[D_];
    #pragma unroll
    for (int d = 0; d < D_; d++) acc[d] = 0.f;
    float mrun = -1e30f, lrun = 0.f;

    __shared__ float Ks[32][64];
    __shared__ float Vs[32][64];

    const int kend = qt * 128 + 127;

    for (int kt = 0; kt <= kend; kt += 32) {
        __syncthreads();
        #pragma unroll
        for (int i = 0; i < 4; i++) {
            const int e  = tid + i * 128;
            const int r  = e >> 4;
            const int c4 = (e & 15) << 2;
            *(float4*)&Ks[r][c4] = *(const float4*)&Kbase[(size_t)(kt + r) * D_ + c4];
            *(float4*)&Vs[r][c4] = *(const float4*)&Vbase[(size_t)(kt + r) * D_ + c4];
        }
        __syncthreads();

        float s[32];
        float tmax = -1e30f;
        #pragma unroll
        for (int j = 0; j < 32; j++) {
            float dot = 0.f;
            #pragma unroll
            for (int d4 = 0; d4 < 16; d4++) {
                float4 kk4 = *(const float4*)&Ks[j][d4 * 4];
                dot += q[d4 * 4 + 0] * kk4.x + q[d4 * 4 + 1] * kk4.y
                     + q[d4 * 4 + 2] * kk4.z + q[d4 * 4 + 3] * kk4.w;
            }
            s[j] = (kt + j <= qi) ? dot : -1e30f;
            tmax = fmaxf(tmax, s[j]);
        }

        const float mnew = fmaxf(mrun, tmax);
        const float corr = exp2f(mrun - mnew);
        float psum = 0.f;
        #pragma unroll
        for (int j = 0; j < 32; j++) {
            s[j] = exp2f(s[j] - mnew);
            psum += s[j];
        }
        lrun = lrun * corr + psum;
        mrun = mnew;

        #pragma unroll
        for (int d = 0; d < D_; d++) acc[d] *= corr;
        #pragma unroll
        for (int j = 0; j < 32; j++) {
            const float p = s[j];
            #pragma unroll
            for (int d4 = 0; d4 < 16; d4++) {
                float4 vv = *(const float4*)&Vs[j][d4 * 4];
                acc[d4 * 4 + 0] += p * vv.x;
                acc[d4 * 4 + 1] += p * vv.y;
                acc[d4 * 4 + 2] += p * vv.z;
                acc[d4 * 4 + 3] += p * vv.w;
            }
        }
    }

    const float inv = 1.f / lrun;
    const int bi = bh / H_;
    const int h  = bh % H_;
    float* Op = &g_O[(((size_t)bi * T_ + qi) * H_ + h) * D_];
    #pragma unroll
    for (int d = 0; d < D_; d += 4) {
        float4 v;
        v.x = acc[d + 0] * inv;
        v.y = acc[d + 1] * inv;
        v.z = acc[d + 2] * inv;
        v.w = acc[d + 3] * inv;
        *(float4*)&Op[d] = v;
    }
}

// ---------------------------------------------------------------------------
// Launch
// ---------------------------------------------------------------------------
extern "C" void kernel_launch(void* const* d_in, const int* in_sizes, int n_in,
                              void* d_out, int out_size)
{
    const float* x  = (const float*)d_in[0];
    const float* Wq = (const float*)d_in[1];
    const float* bq = (const float*)d_in[2];
    const float* Wk = (const float*)d_in[3];
    const float* bk = (const float*)d_in[4];
    const float* Wv = (const float*)d_in[5];
    const float* bv = (const float*)d_in[6];
    const float* Wo = (const float*)d_in[7];
    const float* bo = (const float*)d_in[8];

    static bool attr_set = false;
    if (!attr_set) {
        cudaFuncSetAttribute(tc_gemm_kernel,
                             cudaFuncAttributeMaxDynamicSharedMemorySize, SM_TOTAL);
        attr_set = true;
    }

    // 1. split-precision conversions of x and the weight matrices
    cvt_x_kernel<<<(M_ * C_) / 1024, 1024>>>(x);
    cvt_w_kernel<<<dim3((C_ * C_) / 1024, 4), 1024>>>(Wq, Wk, Wv, Wo);

    // 2. QKV projections on tensor cores (mma.sync bf16 split)
    tc_gemm_kernel<<<dim3(C_ / 128, M_ / 128, 3), 256, SM_TOTAL>>>(
        0, nullptr, bq, bk, bv);

    // 3. causal flash attention (fp32 SIMT)
    flash_attn_kernel<<<dim3(T_ / 128, B_ * H_), 128>>>();

    // 4. convert attention output, then output projection on tensor cores
    cvt_o_kernel<<<(M_ * C_) / 1024, 1024>>>();
    tc_gemm_kernel<<<dim3(C_ / 128, M_ / 128, 1), 256, SM_TOTAL>>>(
        1, (float*)d_out, bo, nullptr, nullptr);
}

// round 6
// speedup vs baseline: 3.7321x; 2.8694x over previous
#include <cuda_runtime.h>
#include <cuda_bf16.h>
#include <cstdint>

// ---------------------------------------------------------------------------
// Problem constants
// ---------------------------------------------------------------------------
#define B_  4
#define T_  2048
#define C_  768
#define H_  12
#define D_  64
#define M_  (B_ * T_)          // 8192
#define QSCALE (0.125f * 1.4426950408889634f)   // 1/sqrt(64) * log2(e)

// ---------------------------------------------------------------------------
// Scratch device globals (allocation-guard-safe)
// ---------------------------------------------------------------------------
__device__ __nv_bfloat16 g_Xhi[(size_t)M_ * C_];
__device__ __nv_bfloat16 g_Xlo[(size_t)M_ * C_];
__device__ __nv_bfloat16 g_Whi[4 * (size_t)C_ * C_];   // Wq,Wk,Wv,Wo
__device__ __nv_bfloat16 g_Wlo[4 * (size_t)C_ * C_];

__device__ __nv_bfloat16 g_Qhi[(size_t)B_ * H_ * T_ * D_];   // [B,H,T,D] pre-scaled
__device__ __nv_bfloat16 g_Qlo[(size_t)B_ * H_ * T_ * D_];
__device__ __nv_bfloat16 g_Khi[(size_t)B_ * H_ * T_ * D_];
__device__ __nv_bfloat16 g_Klo[(size_t)B_ * H_ * T_ * D_];
__device__ __nv_bfloat16 g_Vhi[(size_t)B_ * H_ * T_ * D_];
__device__ __nv_bfloat16 g_Vlo[(size_t)B_ * H_ * T_ * D_];

__device__ __nv_bfloat16 g_Ohi[(size_t)M_ * C_];             // [B,T,C]
__device__ __nv_bfloat16 g_Olo[(size_t)M_ * C_];

// ---------------------------------------------------------------------------
// Warp-MMA helpers
// ---------------------------------------------------------------------------
__device__ __forceinline__ uint32_t smem_u32(const void* p) {
    uint32_t a;
    asm("{ .reg .u64 t; cvta.to.shared.u64 t, %1; cvt.u32.u64 %0, t; }"
        : "=r"(a) : "l"(p));
    return a;
}

__device__ __forceinline__ void ldsm_x4(uint32_t* r, uint32_t addr) {
    asm volatile("ldmatrix.sync.aligned.m8n8.x4.shared.b16 {%0,%1,%2,%3}, [%4];"
                 : "=r"(r[0]), "=r"(r[1]), "=r"(r[2]), "=r"(r[3]) : "r"(addr));
}

__device__ __forceinline__ void ldsm_x4_trans(uint32_t* r, uint32_t addr) {
    asm volatile("ldmatrix.sync.aligned.m8n8.x4.trans.shared.b16 {%0,%1,%2,%3}, [%4];"
                 : "=r"(r[0]), "=r"(r[1]), "=r"(r[2]), "=r"(r[3]) : "r"(addr));
}

__device__ __forceinline__ void mma_bf16(float* c, const uint32_t* a, const uint32_t* b) {
    asm volatile(
        "mma.sync.aligned.m16n8k16.row.col.f32.bf16.bf16.f32 "
        "{%0,%1,%2,%3}, {%4,%5,%6,%7}, {%8,%9}, {%0,%1,%2,%3};"
        : "+f"(c[0]), "+f"(c[1]), "+f"(c[2]), "+f"(c[3])
        : "r"(a[0]), "r"(a[1]), "r"(a[2]), "r"(a[3]), "r"(b[0]), "r"(b[1]));
}

// pack two fp32 -> bf16x2 reg: lo half = first arg, hi half = second arg
__device__ __forceinline__ uint32_t pack_bf16x2(float lo, float hi) {
    uint32_t r;
    asm("cvt.rn.bf16x2.f32 %0, %1, %2;" : "=r"(r) : "f"(hi), "f"(lo));
    return r;
}
__device__ __forceinline__ uint32_t residual_pack(uint32_t hipack, float lo, float hi) {
    float rlo = lo - __uint_as_float(hipack << 16);
    float rhi = hi - __uint_as_float(hipack & 0xFFFF0000u);
    return pack_bf16x2(rlo, rhi);
}

// ---------------------------------------------------------------------------
// Split-precision converters (input x and the 4 weight matrices)
// ---------------------------------------------------------------------------
__global__ void cvt_x_kernel(const float* __restrict__ src) {
    size_t i = (size_t)blockIdx.x * blockDim.x + threadIdx.x;
    float v = src[i];
    __nv_bfloat16 h = __float2bfloat16(v);
    g_Xhi[i] = h;
    g_Xlo[i] = __float2bfloat16(v - __bfloat162float(h));
}

__global__ void cvt_w_kernel(const float* __restrict__ Wq, const float* __restrict__ Wk,
                             const float* __restrict__ Wv, const float* __restrict__ Wo) {
    const float* src = (blockIdx.y == 0) ? Wq : (blockIdx.y == 1) ? Wk
                      : (blockIdx.y == 2) ? Wv : Wo;
    size_t off = (size_t)blockIdx.y * C_ * C_;
    size_t i = (size_t)blockIdx.x * blockDim.x + threadIdx.x;
    float v = src[i];
    __nv_bfloat16 h = __float2bfloat16(v);
    g_Whi[off + i] = h;
    g_Wlo[off + i] = __float2bfloat16(v - __bfloat162float(h));
}

// ---------------------------------------------------------------------------
// GEMM via mma.sync. mode 0: QKV proj -> bf16 hi/lo QKV (Q pre-scaled).
// mode 1: out proj (reads g_Ohi/g_Olo) -> fp32 d_out.
// CTA 128x128, BK=32, 256 threads (8 warps, warp tile 32x64), double-buffered.
// ---------------------------------------------------------------------------
#define BK      32
#define NCHUNK  (C_ / BK)      // 24
#define A_STRIDE 80
#define B_STRIDE 272
#define SM_ALO   10240
#define SM_BHI   20480
#define SM_BLO   29184
#define SM_STAGE 37888
#define SM_TOTAL (2 * SM_STAGE)

__global__ __launch_bounds__(256, 1)
void tc_gemm_kernel(int mode, float* __restrict__ out_final,
                    const float* __restrict__ b0, const float* __restrict__ b1,
                    const float* __restrict__ b2)
{
    extern __shared__ char smem[];
    const uint32_t sb = smem_u32(smem);
    const int tid  = threadIdx.x;
    const int lane = tid & 31;
    const int w    = tid >> 5;
    const int wm   = (w & 3) * 32;
    const int wn   = (w >> 2) * 64;

    const int z    = blockIdx.z;
    const int widx = (mode == 0) ? z : 3;
    const __nv_bfloat16* Ahi = (mode == 0) ? g_Xhi : g_Ohi;
    const __nv_bfloat16* Alo = (mode == 0) ? g_Xlo : g_Olo;
    const __nv_bfloat16* Whi = g_Whi + (size_t)widx * C_ * C_;
    const __nv_bfloat16* Wlo = g_Wlo + (size_t)widx * C_ * C_;
    const float* bias = (mode == 0) ? ((z == 0) ? b0 : (z == 1) ? b1 : b2) : b0;

    const int bm = blockIdx.y * 128;
    const int bn = blockIdx.x * 128;

    float acc[2][8][4];
    #pragma unroll
    for (int i = 0; i < 2; i++)
        #pragma unroll
        for (int j = 0; j < 8; j++)
            #pragma unroll
            for (int r = 0; r < 4; r++) acc[i][j][r] = 0.f;

    const int au = tid & 3;
    const int ar = tid >> 2;
    const int bu = tid & 15;
    const int br = tid >> 4;

    const uint32_t aAddr0 = (uint32_t)((wm + (lane & 15)) * A_STRIDE + (lane >> 4) * 16);
    const uint32_t bAddr0 = (uint32_t)(((lane & 7) + ((lane >> 3) & 1) * 8) * B_STRIDE
                                       + (wn + (lane >> 4) * 8) * 2);

    {
        #pragma unroll
        for (int h = 0; h < 2; h++) {
            const int row = ar + h * 64;
            const size_t ga = (size_t)(bm + row) * C_ + au * 8;
            *(uint4*)(smem + row * A_STRIDE + au * 16)          = *(const uint4*)(Ahi + ga);
            *(uint4*)(smem + SM_ALO + row * A_STRIDE + au * 16) = *(const uint4*)(Alo + ga);
        }
        #pragma unroll
        for (int h = 0; h < 2; h++) {
            const int row = br + h * 16;
            const size_t gb = (size_t)row * C_ + bn + bu * 8;
            *(uint4*)(smem + SM_BHI + row * B_STRIDE + bu * 16) = *(const uint4*)(Whi + gb);
            *(uint4*)(smem + SM_BLO + row * B_STRIDE + bu * 16) = *(const uint4*)(Wlo + gb);
        }
    }
    __syncthreads();

    for (int c = 0; c < NCHUNK; ++c) {
        uint4 nAhi[2], nAlo[2], nBhi[2], nBlo[2];
        if (c + 1 < NCHUNK) {
            const int k0 = (c + 1) * BK;
            #pragma unroll
            for (int h = 0; h < 2; h++) {
                const int row = ar + h * 64;
                const size_t ga = (size_t)(bm + row) * C_ + k0 + au * 8;
                nAhi[h] = *(const uint4*)(Ahi + ga);
                nAlo[h] = *(const uint4*)(Alo + ga);
            }
            #pragma unroll
            for (int h = 0; h < 2; h++) {
                const int row = br + h * 16;
                const size_t gb = (size_t)(k0 + row) * C_ + bn + bu * 8;
                nBhi[h] = *(const uint4*)(Whi + gb);
                nBlo[h] = *(const uint4*)(Wlo + gb);
            }
        }

        const uint32_t stg = sb + (c & 1) * SM_STAGE;
        #pragma unroll
        for (int kk = 0; kk < 2; kk++) {
            uint32_t ah[2][4], al[2][4], bh[8][2], bl[8][2];
            #pragma unroll
            for (int i = 0; i < 2; i++) {
                const uint32_t aoff = aAddr0 + i * 16 * A_STRIDE + kk * 32;
                ldsm_x4(ah[i], stg + aoff);
                ldsm_x4(al[i], stg + SM_ALO + aoff);
            }
            #pragma unroll
            for (int jj = 0; jj < 4; jj++) {
                uint32_t t[4];
                const uint32_t boff = bAddr0 + kk * 16 * B_STRIDE + jj * 32;
                ldsm_x4_trans(t, stg + SM_BHI + boff);
                bh[jj * 2][0] = t[0]; bh[jj * 2][1] = t[1];
                bh[jj * 2 + 1][0] = t[2]; bh[jj * 2 + 1][1] = t[3];
                ldsm_x4_trans(t, stg + SM_BLO + boff);
                bl[jj * 2][0] = t[0]; bl[jj * 2][1] = t[1];
                bl[jj * 2 + 1][0] = t[2]; bl[jj * 2 + 1][1] = t[3];
            }
            #pragma unroll
            for (int i = 0; i < 2; i++)
                #pragma unroll
                for (int j = 0; j < 8; j++) {
                    mma_bf16(acc[i][j], ah[i], bh[j]);
                    mma_bf16(acc[i][j], ah[i], bl[j]);
                    mma_bf16(acc[i][j], al[i], bh[j]);
                }
        }

        if (c + 1 < NCHUNK) {
            char* dst = smem + ((c + 1) & 1) * SM_STAGE;
            #pragma unroll
            for (int h = 0; h < 2; h++) {
                const int row = ar + h * 64;
                *(uint4*)(dst + row * A_STRIDE + au * 16)          = nAhi[h];
                *(uint4*)(dst + SM_ALO + row * A_STRIDE + au * 16) = nAlo[h];
            }
            #pragma unroll
            for (int h = 0; h < 2; h++) {
                const int row = br + h * 16;
                *(uint4*)(dst + SM_BHI + row * B_STRIDE + bu * 16) = nBhi[h];
                *(uint4*)(dst + SM_BLO + row * B_STRIDE + bu * 16) = nBlo[h];
            }
        }
        __syncthreads();
    }

    // ---- epilogue ----
    #pragma unroll
    for (int i = 0; i < 2; i++) {
        const int r0 = bm + wm + i * 16 + (lane >> 2);
        #pragma unroll
        for (int j = 0; j < 8; j++) {
            const int col = bn + wn + j * 8 + (lane & 3) * 2;
            const float bx = bias[col], by = bias[col + 1];
            if (mode == 0) {
                const int h = col >> 6;
                const int d = col & 63;
                __nv_bfloat16* hiA = (z == 0) ? g_Qhi : (z == 1) ? g_Khi : g_Vhi;
                __nv_bfloat16* loA = (z == 0) ? g_Qlo : (z == 1) ? g_Klo : g_Vlo;
                #pragma unroll
                for (int half = 0; half < 2; half++) {
                    const int m  = r0 + half * 8;
                    const int bi = m >> 11;
                    const int tt = m & (T_ - 1);
                    float v0 = acc[i][j][half * 2] + bx;
                    float v1 = acc[i][j][half * 2 + 1] + by;
                    if (z == 0) { v0 *= QSCALE; v1 *= QSCALE; }
                    uint32_t uhi = pack_bf16x2(v0, v1);
                    uint32_t ulo = residual_pack(uhi, v0, v1);
                    const size_t idx = (((size_t)bi * H_ + h) * T_ + tt) * D_ + d;
                    *(uint32_t*)(hiA + idx) = uhi;
                    *(uint32_t*)(loA + idx) = ulo;
                }
            } else {
                #pragma unroll
                for (int half = 0; half < 2; half++) {
                    const int m = r0 + half * 8;
                    float2 v = make_float2(acc[i][j][half * 2] + bx,
                                           acc[i][j][half * 2 + 1] + by);
                    *(float2*)(out_final + (size_t)m * C_ + col) = v;
                }
            }
        }
    }
}

// ---------------------------------------------------------------------------
// Flash attention on mma.sync, split-precision bf16, fp32 softmax.
// grid (16, 48), 256 threads (8 warps x 16 q-rows). K-chunk = 64 keys.
// ---------------------------------------------------------------------------
#define FS_QHI  0
#define FS_QLO  18432
#define FS_KHI  36864
#define FS_KLO  46080
#define FS_VHI  55296
#define FS_VLO  64512
#define FS_TOTAL 73728
#define FSTR 144                 // 72 bf16 row stride (odd 16B multiple)

__global__ __launch_bounds__(256, 1)
void flash_mma_kernel()
{
    extern __shared__ char smem[];
    const uint32_t sb = smem_u32(smem);
    const int tid  = threadIdx.x;
    const int lane = tid & 31;
    const int w    = tid >> 5;
    const int qt   = (int)gridDim.x - 1 - (int)blockIdx.x;   // big tiles first
    const int bh   = blockIdx.y;
    const int q0   = qt * 128;

    const size_t headoff = (size_t)bh * T_ * D_;

    // ---- stage Q tile (128 x 64 hi/lo) ----
    {
        const __nv_bfloat16* Qh = g_Qhi + headoff + (size_t)q0 * D_;
        const __nv_bfloat16* Ql = g_Qlo + headoff + (size_t)q0 * D_;
        #pragma unroll
        for (int i = 0; i < 4; i++) {
            const int e = tid + i * 256;         // 0..1023
            const int row = e >> 3, u = e & 7;
            *(uint4*)(smem + FS_QHI + row * FSTR + u * 16) = *(const uint4*)(Qh + row * 64 + u * 8);
            *(uint4*)(smem + FS_QLO + row * FSTR + u * 16) = *(const uint4*)(Ql + row * 64 + u * 8);
        }
    }
    __syncthreads();

    // ---- Q fragments (held in registers for all chunks) ----
    uint32_t qh[4][4], ql[4][4];
    {
        const uint32_t qa = sb + FS_QHI + (uint32_t)((16 * w + (lane & 15)) * FSTR + (lane >> 4) * 16);
        #pragma unroll
        for (int s = 0; s < 4; s++) {
            ldsm_x4(qh[s], qa + s * 32);
            ldsm_x4(ql[s], qa + s * 32 + (FS_QLO - FS_QHI));
        }
    }

    float O[8][4];
    #pragma unroll
    for (int j = 0; j < 8; j++)
        #pragma unroll
        for (int r = 0; r < 4; r++) O[j][r] = 0.f;
    float m0 = -1e30f, m1 = -1e30f, l0 = 0.f, l1 = 0.f;

    const int wrow = q0 + 16 * w;
    const int r0g  = wrow + (lane >> 2);
    const int r1g  = r0g + 8;

    for (int kt = 0; kt < q0 + 128; kt += 64) {
        __syncthreads();
        {   // stage K/V chunk (64 x 64 hi/lo each)
            const __nv_bfloat16* Kh = g_Khi + headoff + (size_t)kt * D_;
            const __nv_bfloat16* Kl = g_Klo + headoff + (size_t)kt * D_;
            const __nv_bfloat16* Vh = g_Vhi + headoff + (size_t)kt * D_;
            const __nv_bfloat16* Vl = g_Vlo + headoff + (size_t)kt * D_;
            #pragma unroll
            for (int i = 0; i < 2; i++) {
                const int e = tid + i * 256;     // 0..511
                const int row = e >> 3, u = e & 7;
                const size_t g = (size_t)row * 64 + u * 8;
                const uint32_t o = (uint32_t)(row * FSTR + u * 16);
                *(uint4*)(smem + FS_KHI + o) = *(const uint4*)(Kh + g);
                *(uint4*)(smem + FS_KLO + o) = *(const uint4*)(Kl + g);
                *(uint4*)(smem + FS_VHI + o) = *(const uint4*)(Vh + g);
                *(uint4*)(smem + FS_VLO + o) = *(const uint4*)(Vl + g);
            }
        }
        __syncthreads();

        if (kt > wrow + 15) continue;            // chunk fully masked for this warp

        // ---- S = Q K^T (split: hi*hi + hi*lo + lo*hi) ----
        float S[8][4];
        #pragma unroll
        for (int j = 0; j < 8; j++)
            #pragma unroll
            for (int r = 0; r < 4; r++) S[j][r] = 0.f;

        #pragma unroll
        for (int kp = 0; kp < 4; kp++) {
            const uint32_t ka0 = sb + FS_KHI
                + (uint32_t)((kp * 16 + (lane & 15)) * FSTR + (lane >> 4) * 16);
            #pragma unroll
            for (int s = 0; s < 4; s++) {
                uint32_t kh[4], kl[4];
                ldsm_x4(kh, ka0 + s * 32);
                ldsm_x4(kl, ka0 + s * 32 + (FS_KLO - FS_KHI));
                uint32_t be[2] = {kh[0], kh[2]}, bo[2] = {kh[1], kh[3]};
                uint32_t le[2] = {kl[0], kl[2]}, lo_[2] = {kl[1], kl[3]};
                mma_bf16(S[2 * kp],     qh[s], be);
                mma_bf16(S[2 * kp],     qh[s], le);
                mma_bf16(S[2 * kp],     ql[s], be);
                mma_bf16(S[2 * kp + 1], qh[s], bo);
                mma_bf16(S[2 * kp + 1], qh[s], lo_);
                mma_bf16(S[2 * kp + 1], ql[s], bo);
            }
        }

        // ---- causal mask (only near the diagonal) ----
        if (kt + 63 > wrow) {
            #pragma unroll
            for (int j = 0; j < 8; j++) {
                const int c0 = kt + j * 8 + (lane & 3) * 2;
                if (c0 > r0g)     S[j][0] = -1e30f;
                if (c0 + 1 > r0g) S[j][1] = -1e30f;
                if (c0 > r1g)     S[j][2] = -1e30f;
                if (c0 + 1 > r1g) S[j][3] = -1e30f;
            }
        }

        // ---- online softmax (base-2 domain; scale folded into Q) ----
        float vmax0 = -1e30f, vmax1 = -1e30f;
        #pragma unroll
        for (int j = 0; j < 8; j++) {
            vmax0 = fmaxf(vmax0, fmaxf(S[j][0], S[j][1]));
            vmax1 = fmaxf(vmax1, fmaxf(S[j][2], S[j][3]));
        }
        vmax0 = fmaxf(vmax0, __shfl_xor_sync(0xffffffffu, vmax0, 1));
        vmax0 = fmaxf(vmax0, __shfl_xor_sync(0xffffffffu, vmax0, 2));
        vmax1 = fmaxf(vmax1, __shfl_xor_sync(0xffffffffu, vmax1, 1));
        vmax1 = fmaxf(vmax1, __shfl_xor_sync(0xffffffffu, vmax1, 2));

        const float mn0 = fmaxf(m0, vmax0);
        const float mn1 = fmaxf(m1, vmax1);
        const float c0f = exp2f(m0 - mn0);
        const float c1f = exp2f(m1 - mn1);
        m0 = mn0; m1 = mn1;

        float sum0 = 0.f, sum1 = 0.f;
        float P[8][4];
        #pragma unroll
        for (int j = 0; j < 8; j++) {
            P[j][0] = exp2f(S[j][0] - mn0);
            P[j][1] = exp2f(S[j][1] - mn0);
            P[j][2] = exp2f(S[j][2] - mn1);
            P[j][3] = exp2f(S[j][3] - mn1);
            sum0 += P[j][0] + P[j][1];
            sum1 += P[j][2] + P[j][3];
        }
        sum0 += __shfl_xor_sync(0xffffffffu, sum0, 1);
        sum0 += __shfl_xor_sync(0xffffffffu, sum0, 2);
        sum1 += __shfl_xor_sync(0xffffffffu, sum1, 1);
        sum1 += __shfl_xor_sync(0xffffffffu, sum1, 2);
        l0 = l0 * c0f + sum0;
        l1 = l1 * c1f + sum1;

        #pragma unroll
        for (int j = 0; j < 8; j++) {
            O[j][0] *= c0f; O[j][1] *= c0f;
            O[j][2] *= c1f; O[j][3] *= c1f;
        }

        // ---- P fragments (split hi/lo), straight from registers ----
        uint32_t pa_h[4][4], pa_l[4][4];
        #pragma unroll
        for (int kp = 0; kp < 4; kp++) {
            pa_h[kp][0] = pack_bf16x2(P[2 * kp][0],     P[2 * kp][1]);
            pa_h[kp][1] = pack_bf16x2(P[2 * kp][2],     P[2 * kp][3]);
            pa_h[kp][2] = pack_bf16x2(P[2 * kp + 1][0], P[2 * kp + 1][1]);
            pa_h[kp][3] = pack_bf16x2(P[2 * kp + 1][2], P[2 * kp + 1][3]);
            pa_l[kp][0] = residual_pack(pa_h[kp][0], P[2 * kp][0],     P[2 * kp][1]);
            pa_l[kp][1] = residual_pack(pa_h[kp][1], P[2 * kp][2],     P[2 * kp][3]);
            pa_l[kp][2] = residual_pack(pa_h[kp][2], P[2 * kp + 1][0], P[2 * kp + 1][1]);
            pa_l[kp][3] = residual_pack(pa_h[kp][3], P[2 * kp + 1][2], P[2 * kp + 1][3]);
        }

        // ---- O += P V (split: Ph*Vh + Ph*Vl + Pl*Vh) ----
        #pragma unroll
        for (int kp = 0; kp < 4; kp++) {
            const uint32_t va0 = sb + FS_VHI
                + (uint32_t)((kp * 16 + (lane & 7) + ((lane >> 3) & 1) * 8) * FSTR
                             + (lane >> 4) * 16);
            #pragma unroll
            for (int db = 0; db < 4; db++) {
                uint32_t vh[4], vl[4];
                ldsm_x4_trans(vh, va0 + db * 32);
                ldsm_x4_trans(vl, va0 + db * 32 + (FS_VLO - FS_VHI));
                uint32_t bh0[2] = {vh[0], vh[1]}, bh1[2] = {vh[2], vh[3]};
                uint32_t bl0[2] = {vl[0], vl[1]}, bl1[2] = {vl[2], vl[3]};
                mma_bf16(O[2 * db],     pa_h[kp], bh0);
                mma_bf16(O[2 * db],     pa_h[kp], bl0);
                mma_bf16(O[2 * db],     pa_l[kp], bh0);
                mma_bf16(O[2 * db + 1], pa_h[kp], bh1);
                mma_bf16(O[2 * db + 1], pa_h[kp], bl1);
                mma_bf16(O[2 * db + 1], pa_l[kp], bh1);
            }
        }
    }

    // ---- epilogue: normalize, split to bf16 hi/lo, write [B,T,C] ----
    const float inv0 = 1.f / l0;
    const float inv1 = 1.f / l1;
    const int bi = bh / H_;
    const int h  = bh % H_;
    #pragma unroll
    for (int jd = 0; jd < 8; jd++) {
        const int d0 = jd * 8 + (lane & 3) * 2;
        {
            float v0 = O[jd][0] * inv0, v1 = O[jd][1] * inv0;
            uint32_t uhi = pack_bf16x2(v0, v1);
            uint32_t ulo = residual_pack(uhi, v0, v1);
            const size_t idx = ((size_t)bi * T_ + r0g) * C_ + h * 64 + d0;
            *(uint32_t*)(g_Ohi + idx) = uhi;
            *(uint32_t*)(g_Olo + idx) = ulo;
        }
        {
            float v0 = O[jd][2] * inv1, v1 = O[jd][3] * inv1;
            uint32_t uhi = pack_bf16x2(v0, v1);
            uint32_t ulo = residual_pack(uhi, v0, v1);
            const size_t idx = ((size_t)bi * T_ + r1g) * C_ + h * 64 + d0;
            *(uint32_t*)(g_Ohi + idx) = uhi;
            *(uint32_t*)(g_Olo + idx) = ulo;
        }
    }
}

// ---------------------------------------------------------------------------
// Launch
// ---------------------------------------------------------------------------
extern "C" void kernel_launch(void* const* d_in, const int* in_sizes, int n_in,
                              void* d_out, int out_size)
{
    const float* x  = (const float*)d_in[0];
    const float* Wq = (const float*)d_in[1];
    const float* bq = (const float*)d_in[2];
    const float* Wk = (const float*)d_in[3];
    const float* bk = (const float*)d_in[4];
    const float* Wv = (const float*)d_in[5];
    const float* bv = (const float*)d_in[6];
    const float* Wo = (const float*)d_in[7];
    const float* bo = (const float*)d_in[8];

    static bool attr_set = false;
    if (!attr_set) {
        cudaFuncSetAttribute(tc_gemm_kernel,
                             cudaFuncAttributeMaxDynamicSharedMemorySize, SM_TOTAL);
        cudaFuncSetAttribute(flash_mma_kernel,
                             cudaFuncAttributeMaxDynamicSharedMemorySize, FS_TOTAL);
        attr_set = true;
    }

    cvt_x_kernel<<<(M_ * C_) / 1024, 1024>>>(x);
    cvt_w_kernel<<<dim3((C_ * C_) / 1024, 4), 1024>>>(Wq, Wk, Wv, Wo);

    tc_gemm_kernel<<<dim3(C_ / 128, M_ / 128, 3), 256, SM_TOTAL>>>(
        0, nullptr, bq, bk, bv);

    flash_mma_kernel<<<dim3(T_ / 128, B_ * H_), 256, FS_TOTAL>>>();

    tc_gemm_kernel<<<dim3(C_ / 128, M_ / 128, 1), 256, SM_TOTAL>>>(
        1, (float*)d_out, bo, nullptr, nullptr);
}